// round 1
// baseline (speedup 1.0000x reference)
#include <cuda_runtime.h>
#include <cstdint>

// Problem constants (fixed by the dataset problem)
constexpr int B = 64;
constexpr int T = 1024;
constexpr int V = 512;
constexpr int L = 128;
constexpr int S = 2 * L + 1;        // 257 states
constexpr int NSTAGE = 6;           // cp.async row pipeline depth
constexpr int THREADS = 256;

#define NEGV (-1e30f)

__device__ float g_loss[B];         // per-batch loss scratch (device global, no alloc)

__device__ __forceinline__ void cp_async16(uint32_t saddr, const void* gptr) {
    asm volatile("cp.async.cg.shared.global [%0], [%1], 16;\n" ::"r"(saddr), "l"(gptr));
}
__device__ __forceinline__ void cp_commit() {
    asm volatile("cp.async.commit_group;\n");
}
template <int N>
__device__ __forceinline__ void cp_wait() {
    asm volatile("cp.async.wait_group %0;\n" ::"n"(N));
}

__global__ __launch_bounds__(THREADS, 1)
void ctc_alpha_kernel(const float* __restrict__ outputs,
                      const int*   __restrict__ labels,
                      const int*   __restrict__ output_lengths,
                      const int*   __restrict__ label_lengths) {
    // Shared memory
    __shared__ __align__(16) float rowbuf[NSTAGE][V];   // 12 KB
    __shared__ __align__(16) float alpha[2][S + 2];     // +2 front pad of NEG
    __shared__ int   labs[L];
    __shared__ float fin[2];

    const int b   = blockIdx.x;
    const int tid = threadIdx.x;
    const int olen = output_lengths[b];
    const int llen = label_lengths[b];
    const int s0g = 2 * llen - 1;
    const int s1g = 2 * llen;

    // Load labels for this batch
    if (tid < L) labs[tid] = labels[b * L + tid];

    // Front pads (index -2, -1 of the logical alpha) stay NEG forever
    if (tid < 2) {
        alpha[0][tid] = NEGV;
        alpha[1][tid] = NEGV;
    }

    // Prologue: prefetch rows 0 .. NSTAGE-2
    const float* rowg = outputs + (size_t)b * T * V;
    const bool loader = (tid < V / 4);   // 128 threads x 16B = 2KB row
    if (loader) {
        #pragma unroll
        for (int k = 0; k < NSTAGE - 1; ++k) {
            uint32_t sa = (uint32_t)__cvta_generic_to_shared(&rowbuf[k][tid * 4]);
            cp_async16(sa, rowg + (size_t)k * V + tid * 4);
            cp_commit();
        }
    }
    __syncthreads();   // labs + pads visible

    // Per-thread static state info for s = tid
    // ext[s] = BLANK(0) if s even, labels[(s-1)/2] if odd
    // skip[s] = odd s>=3 && labs[li] != labs[li-1]
    int  ext_idx;
    bool skip;
    if (tid & 1) {
        const int li = (tid - 1) >> 1;
        ext_idx = labs[li];
        skip = (li > 0) && (labs[li] != labs[li - 1]);
    } else {
        ext_idx = 0;
        skip = false;
    }

    int cur = 0;
    int rd_stage = 0;                      // stage holding row t
    int wr_stage = NSTAGE - 1;             // stage to receive row t+NSTAGE-1

    for (int t = 0; t < T; ++t) {
        if (loader) cp_wait<NSTAGE - 2>();   // row t landed (issuing threads)
        __syncthreads();                     // block-wide visibility + alpha swap

        const float* row = rowbuf[rd_stage];
        const int nxt = cur ^ 1;

        // --- state s = tid ---
        const float e = row[ext_idx];
        float v;
        if (t == 0) {
            v = (tid <= 1) ? e : NEGV;
        } else {
            // logical alpha index s maps to alpha[buf][s+2]
            const float p0 = alpha[cur][tid + 2];
            const float p1 = alpha[cur][tid + 1];
            const float p2r = alpha[cur][tid + 0];
            const float p2 = skip ? p2r : NEGV;
            const float m  = fmaxf(p0, fmaxf(p1, p2));
            const float sum = __expf(p0 - m) + __expf(p1 - m) + __expf(p2 - m);
            v = m + __logf(sum) + e;
        }
        alpha[nxt][tid + 2] = v;

        // --- state s = 256 (even/blank), handled by thread 0 ---
        float v2 = NEGV;
        if (tid == 0) {
            if (t == 0) {
                v2 = NEGV;
            } else {
                const float p0 = alpha[cur][256 + 2];
                const float p1 = alpha[cur][255 + 2];
                const float m  = fmaxf(p0, p1);
                v2 = m + __logf(__expf(p0 - m) + __expf(p1 - m)) + row[0];
            }
            alpha[nxt][256 + 2] = v2;
        }

        // Record alpha at t == olen-1 for the final states
        if (t == olen - 1) {
            if (tid == s0g) fin[0] = v;
            if (tid == s1g) fin[1] = v;
            if (tid == 0 && s1g == 256) fin[1] = v2;
        }

        // Prefetch row t + NSTAGE - 1 into the stage consumed at iter t-1
        const int tp = t + NSTAGE - 1;
        if (loader && tp < T) {
            uint32_t sa = (uint32_t)__cvta_generic_to_shared(&rowbuf[wr_stage][tid * 4]);
            cp_async16(sa, rowg + (size_t)tp * V + tid * 4);
            cp_commit();
        }

        cur = nxt;
        rd_stage = (rd_stage + 1 == NSTAGE) ? 0 : rd_stage + 1;
        wr_stage = (wr_stage + 1 == NSTAGE) ? 0 : wr_stage + 1;
    }

    __syncthreads();
    if (tid == 0) {
        const float a0 = fin[0];
        const float a1 = fin[1];
        const float m  = fmaxf(a0, a1);
        const float ll = m + logf(expf(a0 - m) + expf(a1 - m));
        g_loss[b] = -ll / (float)llen;
    }
}

// Deterministic fixed-order mean over the 64 per-batch losses.
__global__ void ctc_reduce_kernel(float* __restrict__ out) {
    __shared__ float s[2];
    const int t = threadIdx.x;           // 64 threads
    float v = g_loss[t];
    #pragma unroll
    for (int o = 16; o > 0; o >>= 1)
        v += __shfl_down_sync(0xffffffffu, v, o);
    if ((t & 31) == 0) s[t >> 5] = v;
    __syncthreads();
    if (t == 0) *out = (s[0] + s[1]) * (1.0f / (float)B);
}

extern "C" void kernel_launch(void* const* d_in, const int* in_sizes, int n_in,
                              void* d_out, int out_size) {
    const float* outputs        = (const float*)d_in[0];
    const int*   labels         = (const int*)d_in[1];
    const int*   output_lengths = (const int*)d_in[2];
    const int*   label_lengths  = (const int*)d_in[3];
    float* out = (float*)d_out;

    ctc_alpha_kernel<<<B, THREADS>>>(outputs, labels, output_lengths, label_lengths);
    ctc_reduce_kernel<<<1, 64>>>(out);
}